// round 2
// baseline (speedup 1.0000x reference)
#include <cuda_runtime.h>
#include <cstddef>
#include <math.h>

#define DMODEL 1024
#define DINNER 2048
#define DSTATE 16
#define BATCH  4
#define SEQ    4096
#define MTOT   (BATCH * SEQ)   // 16384 rows
#define KTAPS  64

// ---- scratch (device globals: no allocations allowed) ----
__device__ float g_xproj[(size_t)MTOT * DINNER];   // 128 MB
__device__ float g_gate [(size_t)MTOT * DINNER];   // 128 MB (post-sigmoid)
__device__ float g_u    [(size_t)MTOT * DINNER];   // 128 MB
__device__ float g_impT [KTAPS * DINNER];          // impulse response, [k][c]

// ============================================================
// 1) Impulse response: g_k[c] = C_c . A_c^k . B_c, k = 0..63
//    One thread per channel; h kept in registers.
// ============================================================
__global__ void impulse_kernel(const float* __restrict__ A,
                               const float* __restrict__ Bv,
                               const float* __restrict__ Cv) {
    int c = blockIdx.x * blockDim.x + threadIdx.x;
    if (c >= DINNER) return;
    const float* Ac = A + (size_t)c * DSTATE * DSTATE;
    float h[DSTATE], Cr[DSTATE];
#pragma unroll
    for (int n = 0; n < DSTATE; n++) {
        h[n]  = Bv[c * DSTATE + n];
        Cr[n] = Cv[c * DSTATE + n];
    }
    float y = 0.f;
#pragma unroll
    for (int n = 0; n < DSTATE; n++) y += Cr[n] * h[n];
    g_impT[c] = y;                                   // k = 0: C.B

    for (int k = 1; k < KTAPS; k++) {
        float hn[DSTATE];
#pragma unroll
        for (int n = 0; n < DSTATE; n++) {
            float s = 0.f;
#pragma unroll
            for (int m = 0; m < DSTATE; m++) s += Ac[n * DSTATE + m] * h[m];
            hn[n] = s;
        }
        y = 0.f;
#pragma unroll
        for (int n = 0; n < DSTATE; n++) { h[n] = hn[n]; y += Cr[n] * hn[n]; }
        g_impT[k * DINNER + c] = y;
    }
}

// ============================================================
// 2) SGEMM: C[M,N] = A[M,K] @ B[K,N] + bias  (optional sigmoid)
//    128x128 block tile, 8x8 per-thread micro-tile, BK=8.
// ============================================================
template <bool SIG>
__global__ __launch_bounds__(256)
void sgemm_bias_kernel(const float* __restrict__ A, const float* __restrict__ B,
                       const float* __restrict__ bias, float* __restrict__ C,
                       int M, int N, int K) {
    __shared__ float As[8][128];
    __shared__ float Bs[8][128];

    const int tid = threadIdx.x;
    const int m0 = blockIdx.y * 128;
    const int n0 = blockIdx.x * 128;
    const int ty = tid >> 4;          // 0..15
    const int tx = tid & 15;          // 0..15

    float acc[8][8];
#pragma unroll
    for (int i = 0; i < 8; i++)
#pragma unroll
        for (int j = 0; j < 8; j++) acc[i][j] = 0.f;

    const int ar = tid >> 1;              // 0..127 (A-tile row)
    const int ak = (tid & 1) * 4;         // 0 or 4 (A-tile col group)
    const int bk = tid >> 5;              // 0..7   (B-tile row)
    const int bn = (tid & 31) * 4;        // 0..124 (B-tile col)

    const float* Aptr = A + (size_t)(m0 + ar) * K + ak;
    const float* Bptr = B + (size_t)bk * N + n0 + bn;

    for (int k0 = 0; k0 < K; k0 += 8) {
        float4 av = *(const float4*)(Aptr + k0);
        float4 bv = *(const float4*)(Bptr + (size_t)k0 * N);
        As[ak + 0][ar] = av.x;
        As[ak + 1][ar] = av.y;
        As[ak + 2][ar] = av.z;
        As[ak + 3][ar] = av.w;
        *(float4*)&Bs[bk][bn] = bv;
        __syncthreads();

#pragma unroll
        for (int kk = 0; kk < 8; kk++) {
            float4 a0 = *(const float4*)&As[kk][ty * 8];
            float4 a1 = *(const float4*)&As[kk][ty * 8 + 4];
            float4 b0 = *(const float4*)&Bs[kk][tx * 8];
            float4 b1 = *(const float4*)&Bs[kk][tx * 8 + 4];
            float a[8] = {a0.x, a0.y, a0.z, a0.w, a1.x, a1.y, a1.z, a1.w};
            float b[8] = {b0.x, b0.y, b0.z, b0.w, b1.x, b1.y, b1.z, b1.w};
#pragma unroll
            for (int i = 0; i < 8; i++)
#pragma unroll
                for (int j = 0; j < 8; j++) acc[i][j] += a[i] * b[j];
        }
        __syncthreads();
    }

#pragma unroll
    for (int i = 0; i < 8; i++) {
        const size_t row = (size_t)(m0 + ty * 8 + i);
#pragma unroll
        for (int j = 0; j < 8; j++) {
            const int col = n0 + tx * 8 + j;
            float v = acc[i][j] + bias[col];
            if (SIG) v = 1.0f / (1.0f + expf(-v));
            C[row * N + col] = v;
        }
    }
}

// ============================================================
// 3) Causal 64-tap conv per channel, fused with gating:
//    u[b,s,c] = gate[b,s,c] * sum_k g[c][k] * xproj[b,s-k,c]
//    Block: 128 threads = 128 channels; each thread does 16 s.
// ============================================================
__global__ __launch_bounds__(128)
void conv_gate_kernel() {
    __shared__ float gs[128][KTAPS + 1];   // +1 pad: conflict-free

    const int tid = threadIdx.x;
    const int c  = blockIdx.y * 128 + tid;
    const int s0 = blockIdx.x * 16;
    const int b  = blockIdx.z;

#pragma unroll
    for (int k = 0; k < KTAPS; k++) gs[tid][k] = g_impT[k * DINNER + c];
    // each thread reads only its own row; no cross-thread sync needed

    const float* xp = g_xproj + (size_t)b * SEQ * DINNER;
    float acc[16];
#pragma unroll
    for (int i = 0; i < 16; i++) acc[i] = 0.f;
    const float* grow = gs[tid];

    int jlo = s0 - (KTAPS - 1);
    if (jlo < 0) jlo = 0;
    for (int j = jlo; j <= s0 + 15; j++) {
        const float xv = xp[(size_t)j * DINNER + c];
        const int d = j - s0;          // -63 .. 15
#pragma unroll
        for (int i = 0; i < 16; i++) {
            const int k = i - d;       // tap index = (s0+i) - j
            if (k >= 0 && k < KTAPS) acc[i] += grow[k] * xv;
        }
    }

#pragma unroll
    for (int i = 0; i < 16; i++) {
        const size_t idx = ((size_t)b * SEQ + s0 + i) * DINNER + c;
        g_u[idx] = acc[i] * g_gate[idx];
    }
}

// ============================================================
extern "C" void kernel_launch(void* const* d_in, const int* in_sizes, int n_in,
                              void* d_out, int out_size) {
    const float* x      = (const float*)d_in[0];
    const float* w_in   = (const float*)d_in[1];
    const float* b_in   = (const float*)d_in[2];
    const float* w_gate = (const float*)d_in[3];
    const float* b_gate = (const float*)d_in[4];
    const float* A      = (const float*)d_in[5];
    const float* B_ssm  = (const float*)d_in[6];
    const float* C_ssm  = (const float*)d_in[7];
    const float* w_out  = (const float*)d_in[8];
    const float* b_out  = (const float*)d_in[9];
    float* out = (float*)d_out;

    float *xproj, *gate, *u;
    cudaGetSymbolAddress((void**)&xproj, g_xproj);
    cudaGetSymbolAddress((void**)&gate,  g_gate);
    cudaGetSymbolAddress((void**)&u,     g_u);

    // 1) impulse response (tiny)
    impulse_kernel<<<DINNER / 256, 256>>>(A, B_ssm, C_ssm);

    // 2) input projection + gate GEMMs
    dim3 g1(DINNER / 128, MTOT / 128);
    sgemm_bias_kernel<false><<<g1, 256>>>(x, w_in,   b_in,   xproj, MTOT, DINNER, DMODEL);
    sgemm_bias_kernel<true ><<<g1, 256>>>(x, w_gate, b_gate, gate,  MTOT, DINNER, DMODEL);

    // 3) SSM as 64-tap causal conv, fused with gating
    conv_gate_kernel<<<dim3(SEQ / 16, DINNER / 128, BATCH), 128>>>();

    // 4) output projection
    dim3 g2(DMODEL / 128, MTOT / 128);
    sgemm_bias_kernel<false><<<g2, 256>>>(u, w_out, b_out, out, MTOT, DMODEL, DINNER);
}

// round 6
// speedup vs baseline: 1.3553x; 1.3553x over previous
#include <cuda_runtime.h>
#include <cstddef>
#include <cstdint>
#include <math.h>

#define DMODEL 1024
#define DINNER 2048
#define DSTATE 16
#define BATCH  4
#define SEQ    4096
#define MTOT   (BATCH * SEQ)   // 16384 rows
#define KTAPS  64

// ---- scratch (device globals: no allocations allowed) ----
__device__ float g_xproj[(size_t)MTOT * DINNER];   // 128 MB
__device__ float g_gate [(size_t)MTOT * DINNER];   // 128 MB (post-sigmoid)
__device__ float g_u    [(size_t)MTOT * DINNER];   // 128 MB
__device__ float g_impT [KTAPS * DINNER];          // impulse response, [k][c]

// ============================================================
// 1) Impulse response: g_k[c] = C_c . A_c^k . B_c, k = 0..63
// ============================================================
__global__ void impulse_kernel(const float* __restrict__ A,
                               const float* __restrict__ Bv,
                               const float* __restrict__ Cv) {
    int c = blockIdx.x * blockDim.x + threadIdx.x;
    if (c >= DINNER) return;
    const float* Ac = A + (size_t)c * DSTATE * DSTATE;
    float h[DSTATE], Cr[DSTATE];
#pragma unroll
    for (int n = 0; n < DSTATE; n++) {
        h[n]  = Bv[c * DSTATE + n];
        Cr[n] = Cv[c * DSTATE + n];
    }
    float y = 0.f;
#pragma unroll
    for (int n = 0; n < DSTATE; n++) y += Cr[n] * h[n];
    g_impT[c] = y;

    for (int k = 1; k < KTAPS; k++) {
        float hn[DSTATE];
#pragma unroll
        for (int n = 0; n < DSTATE; n++) {
            float s = 0.f;
#pragma unroll
            for (int m = 0; m < DSTATE; m++) s += Ac[n * DSTATE + m] * h[m];
            hn[n] = s;
        }
        y = 0.f;
#pragma unroll
        for (int n = 0; n < DSTATE; n++) { h[n] = hn[n]; y += Cr[n] * hn[n]; }
        g_impT[k * DINNER + c] = y;
    }
}

// ============================================================
// tf32 split helpers (3xTF32 error compensation)
// ============================================================
__device__ __forceinline__ uint32_t f2tf(float f) {
    uint32_t r;
    asm("cvt.rna.tf32.f32 %0, %1;" : "=r"(r) : "f"(f));
    return r;
}
__device__ __forceinline__ void split_tf(float f, uint32_t& hi, uint32_t& lo) {
    hi = f2tf(f);
    lo = f2tf(f - __uint_as_float(hi));
}

#define MMA_TF32(ACC, A0, A1, A2, A3, B0, B1)                                  \
    asm volatile(                                                              \
        "mma.sync.aligned.m16n8k8.row.col.f32.tf32.tf32.f32 "                  \
        "{%0,%1,%2,%3}, {%4,%5,%6,%7}, {%8,%9}, {%0,%1,%2,%3};\n"              \
        : "+f"((ACC)[0]), "+f"((ACC)[1]), "+f"((ACC)[2]), "+f"((ACC)[3])       \
        : "r"(A0), "r"(A1), "r"(A2), "r"(A3), "r"(B0), "r"(B1))

// ============================================================
// 2) 3xTF32 tensor-core GEMM: C[M,N] = A[M,K] @ B[K,N] + bias
//    128x128x16 block tile, cp.async double buffer,
//    8 warps (2m x 4n), warp tile 64x32, mma.m16n8k8.tf32 x3.
// ============================================================
template <bool SIG>
__global__ __launch_bounds__(256)
void mma_gemm_kernel(const float* __restrict__ A, const float* __restrict__ B,
                     const float* __restrict__ bias, float* __restrict__ C,
                     int M, int N, int K) {
    __shared__ float As[2][128][20];
    __shared__ float Bs[2][16][136];

    const int tid  = threadIdx.x;
    const int warp = tid >> 5, lane = tid & 31;
    const int wm   = warp >> 2;          // 0..1
    const int wn   = warp & 3;           // 0..3
    const int grp  = lane >> 2;          // 0..7
    const int qid  = lane & 3;           // 0..3
    const int m0   = blockIdx.y * 128;
    const int n0   = blockIdx.x * 128;

    float acc[4][4][4];
#pragma unroll
    for (int mi = 0; mi < 4; mi++)
#pragma unroll
        for (int ni = 0; ni < 4; ni++)
#pragma unroll
            for (int f = 0; f < 4; f++) acc[mi][ni][f] = 0.f;

    // tile-load mapping
    const int arow = tid >> 2;           // 0..63 (and +64)
    const int ak4  = (tid & 3) * 4;      // 0,4,8,12
    const int brow = tid >> 5;           // 0..7 (and +8)
    const int bn4  = (tid & 31) * 4;     // 0..124

    const float* Abase = A + (size_t)(m0 + arow) * K + ak4;
    const float* Bbase = B + (size_t)brow * N + n0 + bn4;

#define LOAD_TILE(s, k0)                                                          \
    {                                                                             \
        uint32_t d0 = (uint32_t)__cvta_generic_to_shared(&As[s][arow][ak4]);      \
        uint32_t d1 = (uint32_t)__cvta_generic_to_shared(&As[s][arow + 64][ak4]); \
        const float* s0p = Abase + (k0);                                          \
        const float* s1p = Abase + (size_t)64 * K + (k0);                         \
        asm volatile("cp.async.cg.shared.global [%0], [%1], 16;\n" ::"r"(d0), "l"(s0p)); \
        asm volatile("cp.async.cg.shared.global [%0], [%1], 16;\n" ::"r"(d1), "l"(s1p)); \
        uint32_t d2 = (uint32_t)__cvta_generic_to_shared(&Bs[s][brow][bn4]);      \
        uint32_t d3 = (uint32_t)__cvta_generic_to_shared(&Bs[s][brow + 8][bn4]);  \
        const float* s2p = Bbase + (size_t)(k0) * N;                              \
        const float* s3p = Bbase + (size_t)((k0) + 8) * N;                        \
        asm volatile("cp.async.cg.shared.global [%0], [%1], 16;\n" ::"r"(d2), "l"(s2p)); \
        asm volatile("cp.async.cg.shared.global [%0], [%1], 16;\n" ::"r"(d3), "l"(s3p)); \
    }

    const int KT = K / 16;
    LOAD_TILE(0, 0);
    asm volatile("cp.async.commit_group;\n" ::);

    for (int kt = 0; kt < KT; kt++) {
        if (kt + 1 < KT) {
            LOAD_TILE((kt + 1) & 1, (kt + 1) * 16);
            asm volatile("cp.async.commit_group;\n" ::);
            asm volatile("cp.async.wait_group 1;\n" ::);
        } else {
            asm volatile("cp.async.wait_group 0;\n" ::);
        }
        __syncthreads();

        const int s = kt & 1;
#pragma unroll
        for (int kk = 0; kk < 16; kk += 8) {
            uint32_t afh[4][4], afl[4][4], bfh[4][2], bfl[4][2];
#pragma unroll
            for (int mi = 0; mi < 4; mi++) {
                const int r = wm * 64 + mi * 16 + grp;
                split_tf(As[s][r][kk + qid],         afh[mi][0], afl[mi][0]);
                split_tf(As[s][r + 8][kk + qid],     afh[mi][1], afl[mi][1]);
                split_tf(As[s][r][kk + qid + 4],     afh[mi][2], afl[mi][2]);
                split_tf(As[s][r + 8][kk + qid + 4], afh[mi][3], afl[mi][3]);
            }
#pragma unroll
            for (int ni = 0; ni < 4; ni++) {
                const int cn = wn * 32 + ni * 8 + grp;
                split_tf(Bs[s][kk + qid][cn],     bfh[ni][0], bfl[ni][0]);
                split_tf(Bs[s][kk + qid + 4][cn], bfh[ni][1], bfl[ni][1]);
            }
#pragma unroll
            for (int mi = 0; mi < 4; mi++)
#pragma unroll
                for (int ni = 0; ni < 4; ni++) {
                    // cross terms first, dominant term last
                    MMA_TF32(acc[mi][ni], afh[mi][0], afh[mi][1], afh[mi][2], afh[mi][3],
                             bfl[ni][0], bfl[ni][1]);
                    MMA_TF32(acc[mi][ni], afl[mi][0], afl[mi][1], afl[mi][2], afl[mi][3],
                             bfh[ni][0], bfh[ni][1]);
                    MMA_TF32(acc[mi][ni], afh[mi][0], afh[mi][1], afh[mi][2], afh[mi][3],
                             bfh[ni][0], bfh[ni][1]);
                }
        }
        __syncthreads();
    }

    // epilogue
#pragma unroll
    for (int mi = 0; mi < 4; mi++) {
        const int row = m0 + wm * 64 + mi * 16 + grp;
#pragma unroll
        for (int ni = 0; ni < 4; ni++) {
            const int col = n0 + wn * 32 + ni * 8 + 2 * qid;
            const float b0 = bias[col], b1 = bias[col + 1];
            float v0 = acc[mi][ni][0] + b0;
            float v1 = acc[mi][ni][1] + b1;
            float v2 = acc[mi][ni][2] + b0;
            float v3 = acc[mi][ni][3] + b1;
            if (SIG) {
                v0 = 1.0f / (1.0f + expf(-v0));
                v1 = 1.0f / (1.0f + expf(-v1));
                v2 = 1.0f / (1.0f + expf(-v2));
                v3 = 1.0f / (1.0f + expf(-v3));
            }
            *(float2*)(C + (size_t)row * N + col)       = make_float2(v0, v1);
            *(float2*)(C + (size_t)(row + 8) * N + col) = make_float2(v2, v3);
        }
    }
#undef LOAD_TILE
}

// ============================================================
// 3) Causal 64-tap conv + gate. Taps in registers, fully
//    unrolled d-loop -> compile-time predicates (no ALU preds).
// ============================================================
__global__ __launch_bounds__(128, 4)
void conv_gate_kernel() {
    const int tid = threadIdx.x;
    const int c   = blockIdx.y * 128 + tid;
    const int s0  = blockIdx.x * 16;
    const int b   = blockIdx.z;

    float gk[KTAPS];
#pragma unroll
    for (int k = 0; k < KTAPS; k++) gk[k] = g_impT[k * DINNER + c];

    const float* xp = g_xproj + (size_t)b * SEQ * DINNER + c;
    float acc[16];
#pragma unroll
    for (int i = 0; i < 16; i++) acc[i] = 0.f;

    if (s0 >= KTAPS - 1) {
        // steady state: all predicates compile-time
#pragma unroll
        for (int d = -(KTAPS - 1); d <= 15; d++) {
            const float xv = xp[(size_t)(s0 + d) * DINNER];
#pragma unroll
            for (int i = 0; i < 16; i++) {
                const int k = i - d;
                if (k >= 0 && k < KTAPS) acc[i] += gk[k] * xv;
            }
        }
    } else {
        for (int j = 0; j <= s0 + 15; j++) {
            const float xv = xp[(size_t)j * DINNER];
            const int d = j - s0;
#pragma unroll
            for (int i = 0; i < 16; i++) {
                const int k = i - d;
                if (k >= 0 && k < KTAPS) acc[i] += gk[k] * xv;
            }
        }
    }

#pragma unroll
    for (int i = 0; i < 16; i++) {
        const size_t idx = ((size_t)b * SEQ + s0 + i) * DINNER + c;
        g_u[idx] = acc[i] * g_gate[idx];
    }
}

// ============================================================
extern "C" void kernel_launch(void* const* d_in, const int* in_sizes, int n_in,
                              void* d_out, int out_size) {
    const float* x      = (const float*)d_in[0];
    const float* w_in   = (const float*)d_in[1];
    const float* b_in   = (const float*)d_in[2];
    const float* w_gate = (const float*)d_in[3];
    const float* b_gate = (const float*)d_in[4];
    const float* A      = (const float*)d_in[5];
    const float* B_ssm  = (const float*)d_in[6];
    const float* C_ssm  = (const float*)d_in[7];
    const float* w_out  = (const float*)d_in[8];
    const float* b_out  = (const float*)d_in[9];
    float* out = (float*)d_out;

    float *xproj, *gate, *u;
    cudaGetSymbolAddress((void**)&xproj, g_xproj);
    cudaGetSymbolAddress((void**)&gate,  g_gate);
    cudaGetSymbolAddress((void**)&u,     g_u);

    // 1) impulse response (tiny)
    impulse_kernel<<<DINNER / 256, 256>>>(A, B_ssm, C_ssm);

    // 2) input projection + gate GEMMs (3xTF32 tensor cores)
    dim3 g1(DINNER / 128, MTOT / 128);
    mma_gemm_kernel<false><<<g1, 256>>>(x, w_in,   b_in,   xproj, MTOT, DINNER, DMODEL);
    mma_gemm_kernel<true ><<<g1, 256>>>(x, w_gate, b_gate, gate,  MTOT, DINNER, DMODEL);

    // 3) SSM as 64-tap causal conv, fused with gating
    conv_gate_kernel<<<dim3(SEQ / 16, DINNER / 128, BATCH), 128>>>();

    // 4) output projection
    dim3 g2(DMODEL / 128, MTOT / 128);
    mma_gemm_kernel<false><<<g2, 256>>>(u, w_out, b_out, out, MTOT, DMODEL, DINNER);
}

// round 11
// speedup vs baseline: 2.3593x; 1.7407x over previous
#include <cuda_runtime.h>
#include <cuda_bf16.h>
#include <cstddef>
#include <cstdint>
#include <math.h>

#define DMODEL 1024
#define DINNER 2048
#define DSTATE 16
#define BATCH  4
#define SEQ    4096
#define MTOT   (BATCH * SEQ)   // 16384 rows
#define KTAPS  64

#define BK 32                     // bf16 elems per K-chunk (64B/row)
#define ROWP 40                   // padded smem row length (80B) -> conflict-free
#define TILE_ELEMS (128 * ROWP)   // one operand tile (bf16 elems)
#define SMEM_BYTES (2 * 4 * TILE_ELEMS * 2)   // 2 stages x 4 tiles = 81920 B

// ---- scratch (device globals: no allocations allowed) ----
__device__ float g_xproj[(size_t)MTOT * DINNER];
__device__ float g_gate [(size_t)MTOT * DINNER];
__device__ __nv_bfloat16 g_xhi[(size_t)MTOT * DMODEL];
__device__ __nv_bfloat16 g_xlo[(size_t)MTOT * DMODEL];
__device__ __nv_bfloat16 g_uhi[(size_t)MTOT * DINNER];
__device__ __nv_bfloat16 g_ulo[(size_t)MTOT * DINNER];
__device__ __nv_bfloat16 g_wiT_hi[(size_t)DINNER * DMODEL];
__device__ __nv_bfloat16 g_wiT_lo[(size_t)DINNER * DMODEL];
__device__ __nv_bfloat16 g_wgT_hi[(size_t)DINNER * DMODEL];
__device__ __nv_bfloat16 g_wgT_lo[(size_t)DINNER * DMODEL];
__device__ __nv_bfloat16 g_woT_hi[(size_t)DMODEL * DINNER];
__device__ __nv_bfloat16 g_woT_lo[(size_t)DMODEL * DINNER];
__device__ float g_impT[KTAPS * DINNER];

// ============================================================
// helpers
// ============================================================
#define CP16(dst, src) \
    asm volatile("cp.async.cg.shared.global [%0], [%1], 16;\n" ::"r"(dst), "l"(src))

#define LDM4(R, addr)                                                          \
    asm volatile("ldmatrix.sync.aligned.m8n8.x4.shared.b16 {%0,%1,%2,%3}, [%4];" \
                 : "=r"((R)[0]), "=r"((R)[1]), "=r"((R)[2]), "=r"((R)[3])      \
                 : "r"(addr))

#define MMA_BF16(ACC, A, B0, B1)                                               \
    asm volatile(                                                              \
        "mma.sync.aligned.m16n8k16.row.col.f32.bf16.bf16.f32 "                 \
        "{%0,%1,%2,%3}, {%4,%5,%6,%7}, {%8,%9}, {%0,%1,%2,%3};\n"              \
        : "+f"((ACC)[0]), "+f"((ACC)[1]), "+f"((ACC)[2]), "+f"((ACC)[3])       \
        : "r"((A)[0]), "r"((A)[1]), "r"((A)[2]), "r"((A)[3]), "r"(B0), "r"(B1))

// ============================================================
// prep: split x -> bf16 hi/lo (same layout)
// ============================================================
__global__ void split_kernel(const float* __restrict__ src,
                             __nv_bfloat16* __restrict__ hi,
                             __nv_bfloat16* __restrict__ lo, size_t n) {
    size_t i = ((size_t)blockIdx.x * blockDim.x + threadIdx.x) * 4;
    if (i >= n) return;
    float4 v = *(const float4*)(src + i);
    __nv_bfloat16 h0 = __float2bfloat16(v.x), h1 = __float2bfloat16(v.y);
    __nv_bfloat16 h2 = __float2bfloat16(v.z), h3 = __float2bfloat16(v.w);
    *(__nv_bfloat162*)(hi + i)     = __nv_bfloat162(h0, h1);
    *(__nv_bfloat162*)(hi + i + 2) = __nv_bfloat162(h2, h3);
    *(__nv_bfloat162*)(lo + i) =
        __nv_bfloat162(__float2bfloat16(v.x - __bfloat162float(h0)),
                       __float2bfloat16(v.y - __bfloat162float(h1)));
    *(__nv_bfloat162*)(lo + i + 2) =
        __nv_bfloat162(__float2bfloat16(v.z - __bfloat162float(h2)),
                       __float2bfloat16(v.w - __bfloat162float(h3)));
}

// W[K][N] -> WT_hi/lo [N][K] bf16, tiled smem transpose
__global__ void wprep_kernel(const float* __restrict__ W,
                             __nv_bfloat16* __restrict__ WT_hi,
                             __nv_bfloat16* __restrict__ WT_lo, int K, int N) {
    __shared__ float t[32][33];
    const int tx = threadIdx.x, ty = threadIdx.y;
    const int n0 = blockIdx.x * 32, k0 = blockIdx.y * 32;
#pragma unroll
    for (int i = 0; i < 4; i++)
        t[ty + 8 * i][tx] = W[(size_t)(k0 + ty + 8 * i) * N + n0 + tx];
    __syncthreads();
#pragma unroll
    for (int i = 0; i < 4; i++) {
        float v = t[tx][ty + 8 * i];
        __nv_bfloat16 h = __float2bfloat16(v);
        size_t idx = (size_t)(n0 + ty + 8 * i) * K + k0 + tx;
        WT_hi[idx] = h;
        WT_lo[idx] = __float2bfloat16(v - __bfloat162float(h));
    }
}

// ============================================================
// impulse response: g_k[c] = C_c . A_c^k . B_c
// ============================================================
__global__ void impulse_kernel(const float* __restrict__ A,
                               const float* __restrict__ Bv,
                               const float* __restrict__ Cv) {
    int c = blockIdx.x * blockDim.x + threadIdx.x;
    if (c >= DINNER) return;
    const float* Ac = A + (size_t)c * DSTATE * DSTATE;
    float h[DSTATE], Cr[DSTATE];
#pragma unroll
    for (int n = 0; n < DSTATE; n++) {
        h[n]  = Bv[c * DSTATE + n];
        Cr[n] = Cv[c * DSTATE + n];
    }
    float y = 0.f;
#pragma unroll
    for (int n = 0; n < DSTATE; n++) y += Cr[n] * h[n];
    g_impT[c] = y;
    for (int k = 1; k < KTAPS; k++) {
        float hn[DSTATE];
#pragma unroll
        for (int n = 0; n < DSTATE; n++) {
            float s = 0.f;
#pragma unroll
            for (int m = 0; m < DSTATE; m++) s += Ac[n * DSTATE + m] * h[m];
            hn[n] = s;
        }
        y = 0.f;
#pragma unroll
        for (int n = 0; n < DSTATE; n++) { h[n] = hn[n]; y += Cr[n] * hn[n]; }
        g_impT[k * DINNER + c] = y;
    }
}

// ============================================================
// bf16x3 GEMM: C[M,N] = (Ah+Al)[M,K] @ (Bh+Bl)[N,K]^T + bias
// Both operands K-major. 128x128 block, BK=32, double-buffered
// cp.async, ldmatrix fragment loads, mma.m16n8k16.bf16 x3 terms.
// ============================================================
template <bool SIG>
__global__ __launch_bounds__(256)
void bf16x3_gemm(const __nv_bfloat16* __restrict__ Ah,
                 const __nv_bfloat16* __restrict__ Al,
                 const __nv_bfloat16* __restrict__ Bh,
                 const __nv_bfloat16* __restrict__ Bl,
                 const float* __restrict__ bias, float* __restrict__ C,
                 int M, int N, int K) {
    extern __shared__ __nv_bfloat16 sm[];
    const uint32_t sm0 = (uint32_t)__cvta_generic_to_shared(sm);

    const int tid = threadIdx.x, warp = tid >> 5, lane = tid & 31;
    const int wm = warp >> 2, wn = warp & 3;
    const int grp = lane >> 2, qid = lane & 3;
    const int m0 = blockIdx.y * 128, n0 = blockIdx.x * 128;

    float acc[4][4][4];
#pragma unroll
    for (int mi = 0; mi < 4; mi++)
#pragma unroll
        for (int ni = 0; ni < 4; ni++)
#pragma unroll
            for (int f = 0; f < 4; f++) acc[mi][ni][f] = 0.f;

    // cp.async mapping: thread -> (row, 32B half)
    const int lrow = tid >> 1, lhalf = tid & 1;
    const __nv_bfloat16* gsrc[4] = {Ah + (size_t)m0 * K, Al + (size_t)m0 * K,
                                    Bh + (size_t)n0 * K, Bl + (size_t)n0 * K};

    // ldmatrix per-lane address components
    const int q = lane >> 3, lr = lane & 7;
    const int a_row = (q & 1) * 8 + lr, a_cb = (q >> 1) * 16;  // A tiles
    const int b_row = (q >> 1) * 8 + lr, b_cb = (q & 1) * 16;  // B tiles

#define TBASE(s, t) (sm0 + (uint32_t)(((s) * 4 + (t)) * TILE_ELEMS * 2))
#define LOAD_CHUNK(s, c)                                                       \
    {                                                                          \
        _Pragma("unroll")                                                      \
        for (int t = 0; t < 4; t++) {                                          \
            const __nv_bfloat16* src =                                         \
                gsrc[t] + (size_t)lrow * K + (c) * BK + lhalf * 16;            \
            const uint32_t dst = TBASE(s, t) + lrow * 80 + lhalf * 32;         \
            CP16(dst, src);                                                    \
            CP16(dst + 16, src + 8);                                           \
        }                                                                      \
        asm volatile("cp.async.commit_group;\n" ::);                           \
    }

    const int KT = K / BK;
    LOAD_CHUNK(0, 0);

    for (int kt = 0; kt < KT; kt++) {
        if (kt + 1 < KT) {
            LOAD_CHUNK((kt + 1) & 1, kt + 1);
            asm volatile("cp.async.wait_group 1;\n" ::);
        } else {
            asm volatile("cp.async.wait_group 0;\n" ::);
        }
        __syncthreads();

        const int s = kt & 1;
#pragma unroll
        for (int kk = 0; kk < 2; kk++) {                 // two k16 steps
            uint32_t ah[4][4], al[4][4], bh[2][4], bl[2][4];
#pragma unroll
            for (int mi = 0; mi < 4; mi++) {
                const uint32_t ro = (uint32_t)(wm * 64 + mi * 16 + a_row) * 80 +
                                    a_cb + kk * 32;
                LDM4(ah[mi], TBASE(s, 0) + ro);
                LDM4(al[mi], TBASE(s, 1) + ro);
            }
#pragma unroll
            for (int p = 0; p < 2; p++) {
                const uint32_t ro = (uint32_t)(wn * 32 + p * 16 + b_row) * 80 +
                                    b_cb + kk * 32;
                LDM4(bh[p], TBASE(s, 2) + ro);
                LDM4(bl[p], TBASE(s, 3) + ro);
            }
#pragma unroll
            for (int mi = 0; mi < 4; mi++)
#pragma unroll
                for (int ni = 0; ni < 4; ni++) {
                    const int p = ni >> 1, o = (ni & 1) * 2;
                    MMA_BF16(acc[mi][ni], ah[mi], bl[p][o], bl[p][o + 1]);
                    MMA_BF16(acc[mi][ni], al[mi], bh[p][o], bh[p][o + 1]);
                    MMA_BF16(acc[mi][ni], ah[mi], bh[p][o], bh[p][o + 1]);
                }
        }
        __syncthreads();
    }

    // epilogue
#pragma unroll
    for (int mi = 0; mi < 4; mi++) {
        const int row = m0 + wm * 64 + mi * 16 + grp;
#pragma unroll
        for (int ni = 0; ni < 4; ni++) {
            const int col = n0 + wn * 32 + ni * 8 + 2 * qid;
            const float b0 = bias[col], b1 = bias[col + 1];
            float v0 = acc[mi][ni][0] + b0;
            float v1 = acc[mi][ni][1] + b1;
            float v2 = acc[mi][ni][2] + b0;
            float v3 = acc[mi][ni][3] + b1;
            if (SIG) {
                v0 = 1.0f / (1.0f + expf(-v0));
                v1 = 1.0f / (1.0f + expf(-v1));
                v2 = 1.0f / (1.0f + expf(-v2));
                v3 = 1.0f / (1.0f + expf(-v3));
            }
            *(float2*)(C + (size_t)row * N + col)       = make_float2(v0, v1);
            *(float2*)(C + (size_t)(row + 8) * N + col) = make_float2(v2, v3);
        }
    }
#undef LOAD_CHUNK
#undef TBASE
}

// ============================================================
// causal 64-tap conv + gate; writes bf16-split u_hi/u_lo
// ============================================================
__global__ __launch_bounds__(128, 4)
void conv_gate_kernel() {
    const int tid = threadIdx.x;
    const int c   = blockIdx.y * 128 + tid;
    const int s0  = blockIdx.x * 16;
    const int b   = blockIdx.z;

    float gk[KTAPS];
#pragma unroll
    for (int k = 0; k < KTAPS; k++) gk[k] = g_impT[k * DINNER + c];

    const float* xp = g_xproj + (size_t)b * SEQ * DINNER + c;
    float acc[16];
#pragma unroll
    for (int i = 0; i < 16; i++) acc[i] = 0.f;

    if (s0 >= KTAPS - 1) {
#pragma unroll
        for (int d = -(KTAPS - 1); d <= 15; d++) {
            const float xv = xp[(size_t)(s0 + d) * DINNER];
#pragma unroll
            for (int i = 0; i < 16; i++) {
                const int k = i - d;
                if (k >= 0 && k < KTAPS) acc[i] += gk[k] * xv;
            }
        }
    } else {
        for (int j = 0; j <= s0 + 15; j++) {
            const float xv = xp[(size_t)j * DINNER];
            const int d = j - s0;
#pragma unroll
            for (int i = 0; i < 16; i++) {
                const int k = i - d;
                if (k >= 0 && k < KTAPS) acc[i] += gk[k] * xv;
            }
        }
    }

#pragma unroll
    for (int i = 0; i < 16; i++) {
        const size_t idx = ((size_t)b * SEQ + s0 + i) * DINNER + c;
        const float v = acc[i] * g_gate[idx];
        const __nv_bfloat16 h = __float2bfloat16(v);
        g_uhi[idx] = h;
        g_ulo[idx] = __float2bfloat16(v - __bfloat162float(h));
    }
}

// ============================================================
extern "C" void kernel_launch(void* const* d_in, const int* in_sizes, int n_in,
                              void* d_out, int out_size) {
    const float* x      = (const float*)d_in[0];
    const float* w_in   = (const float*)d_in[1];
    const float* b_in   = (const float*)d_in[2];
    const float* w_gate = (const float*)d_in[3];
    const float* b_gate = (const float*)d_in[4];
    const float* A      = (const float*)d_in[5];
    const float* B_ssm  = (const float*)d_in[6];
    const float* C_ssm  = (const float*)d_in[7];
    const float* w_out  = (const float*)d_in[8];
    const float* b_out  = (const float*)d_in[9];
    float* out = (float*)d_out;

    float *xproj, *gate;
    __nv_bfloat16 *xhi, *xlo, *uhi, *ulo;
    __nv_bfloat16 *wiT_hi, *wiT_lo, *wgT_hi, *wgT_lo, *woT_hi, *woT_lo;
    cudaGetSymbolAddress((void**)&xproj,  g_xproj);
    cudaGetSymbolAddress((void**)&gate,   g_gate);
    cudaGetSymbolAddress((void**)&xhi,    g_xhi);
    cudaGetSymbolAddress((void**)&xlo,    g_xlo);
    cudaGetSymbolAddress((void**)&uhi,    g_uhi);
    cudaGetSymbolAddress((void**)&ulo,    g_ulo);
    cudaGetSymbolAddress((void**)&wiT_hi, g_wiT_hi);
    cudaGetSymbolAddress((void**)&wiT_lo, g_wiT_lo);
    cudaGetSymbolAddress((void**)&wgT_hi, g_wgT_hi);
    cudaGetSymbolAddress((void**)&wgT_lo, g_wgT_lo);
    cudaGetSymbolAddress((void**)&woT_hi, g_woT_hi);
    cudaGetSymbolAddress((void**)&woT_lo, g_woT_lo);

    cudaFuncSetAttribute(bf16x3_gemm<false>,
                         cudaFuncAttributeMaxDynamicSharedMemorySize, SMEM_BYTES);
    cudaFuncSetAttribute(bf16x3_gemm<true>,
                         cudaFuncAttributeMaxDynamicSharedMemorySize, SMEM_BYTES);

    // prep
    const size_t nx = (size_t)MTOT * DMODEL;
    split_kernel<<<(unsigned)((nx / 4 + 255) / 256), 256>>>(x, xhi, xlo, nx);
    wprep_kernel<<<dim3(DINNER / 32, DMODEL / 32), dim3(32, 8)>>>(w_in,   wiT_hi, wiT_lo, DMODEL, DINNER);
    wprep_kernel<<<dim3(DINNER / 32, DMODEL / 32), dim3(32, 8)>>>(w_gate, wgT_hi, wgT_lo, DMODEL, DINNER);
    wprep_kernel<<<dim3(DMODEL / 32, DINNER / 32), dim3(32, 8)>>>(w_out,  woT_hi, woT_lo, DINNER, DMODEL);
    impulse_kernel<<<DINNER / 256, 256>>>(A, B_ssm, C_ssm);

    // GEMM1/2
    dim3 g1(DINNER / 128, MTOT / 128);
    bf16x3_gemm<false><<<g1, 256, SMEM_BYTES>>>(xhi, xlo, wiT_hi, wiT_lo, b_in,
                                                xproj, MTOT, DINNER, DMODEL);
    bf16x3_gemm<true ><<<g1, 256, SMEM_BYTES>>>(xhi, xlo, wgT_hi, wgT_lo, b_gate,
                                                gate, MTOT, DINNER, DMODEL);

    // SSM as 64-tap conv + gating (writes split u)
    conv_gate_kernel<<<dim3(SEQ / 16, DINNER / 128, BATCH), 128>>>();

    // GEMM3
    dim3 g2(DMODEL / 128, MTOT / 128);
    bf16x3_gemm<false><<<g2, 256, SMEM_BYTES>>>(uhi, ulo, woT_hi, woT_lo, b_out,
                                                out, MTOT, DMODEL, DINNER);
}

// round 13
// speedup vs baseline: 2.5291x; 1.0720x over previous
#include <cuda_runtime.h>
#include <cuda_bf16.h>
#include <cstddef>
#include <cstdint>
#include <math.h>

#define DMODEL 1024
#define DINNER 2048
#define DSTATE 16
#define BATCH  4
#define SEQ    4096
#define MTOT   (BATCH * SEQ)   // 16384 rows
#define KTAPS  64

#define BK 32                     // bf16 elems per K-chunk (64B/row)
#define TILE_B 8192               // 128 rows x 64B, XOR-swizzled
#define STAGES 3
#define SMEM_BYTES (STAGES * 4 * TILE_B)   // 96 KB -> 2 CTAs/SM

// ---- scratch (device globals: no allocations allowed) ----
__device__ float g_xproj[(size_t)MTOT * DINNER];
__device__ float g_gate [(size_t)MTOT * DINNER];
__device__ __nv_bfloat16 g_xhi[(size_t)MTOT * DMODEL];
__device__ __nv_bfloat16 g_xlo[(size_t)MTOT * DMODEL];
__device__ __nv_bfloat16 g_uhi[(size_t)MTOT * DINNER];
__device__ __nv_bfloat16 g_ulo[(size_t)MTOT * DINNER];
__device__ __nv_bfloat16 g_wiT_hi[(size_t)DINNER * DMODEL];
__device__ __nv_bfloat16 g_wiT_lo[(size_t)DINNER * DMODEL];
__device__ __nv_bfloat16 g_wgT_hi[(size_t)DINNER * DMODEL];
__device__ __nv_bfloat16 g_wgT_lo[(size_t)DINNER * DMODEL];
__device__ __nv_bfloat16 g_woT_hi[(size_t)DMODEL * DINNER];
__device__ __nv_bfloat16 g_woT_lo[(size_t)DMODEL * DINNER];
__device__ float g_impT[KTAPS * DINNER];

// ============================================================
// helpers
// ============================================================
#define CP16(dst, src) \
    asm volatile("cp.async.cg.shared.global [%0], [%1], 16;\n" ::"r"(dst), "l"(src))

#define LDM4(R, addr)                                                          \
    asm volatile("ldmatrix.sync.aligned.m8n8.x4.shared.b16 {%0,%1,%2,%3}, [%4];" \
                 : "=r"((R)[0]), "=r"((R)[1]), "=r"((R)[2]), "=r"((R)[3])      \
                 : "r"(addr))

#define MMA_BF16(ACC, A, B0, B1)                                               \
    asm volatile(                                                              \
        "mma.sync.aligned.m16n8k16.row.col.f32.bf16.bf16.f32 "                 \
        "{%0,%1,%2,%3}, {%4,%5,%6,%7}, {%8,%9}, {%0,%1,%2,%3};\n"              \
        : "+f"((ACC)[0]), "+f"((ACC)[1]), "+f"((ACC)[2]), "+f"((ACC)[3])       \
        : "r"((A)[0]), "r"((A)[1]), "r"((A)[2]), "r"((A)[3]), "r"(B0), "r"(B1))

// ============================================================
// prep: split x -> bf16 hi/lo (same layout)
// ============================================================
__global__ void split_kernel(const float* __restrict__ src,
                             __nv_bfloat16* __restrict__ hi,
                             __nv_bfloat16* __restrict__ lo, size_t n) {
    size_t i = ((size_t)blockIdx.x * blockDim.x + threadIdx.x) * 4;
    if (i >= n) return;
    float4 v = *(const float4*)(src + i);
    __nv_bfloat16 h0 = __float2bfloat16(v.x), h1 = __float2bfloat16(v.y);
    __nv_bfloat16 h2 = __float2bfloat16(v.z), h3 = __float2bfloat16(v.w);
    *(__nv_bfloat162*)(hi + i)     = __nv_bfloat162(h0, h1);
    *(__nv_bfloat162*)(hi + i + 2) = __nv_bfloat162(h2, h3);
    *(__nv_bfloat162*)(lo + i) =
        __nv_bfloat162(__float2bfloat16(v.x - __bfloat162float(h0)),
                       __float2bfloat16(v.y - __bfloat162float(h1)));
    *(__nv_bfloat162*)(lo + i + 2) =
        __nv_bfloat162(__float2bfloat16(v.z - __bfloat162float(h2)),
                       __float2bfloat16(v.w - __bfloat162float(h3)));
}

// W[K][N] -> WT_hi/lo [N][K] bf16, tiled smem transpose
__global__ void wprep_kernel(const float* __restrict__ W,
                             __nv_bfloat16* __restrict__ WT_hi,
                             __nv_bfloat16* __restrict__ WT_lo, int K, int N) {
    __shared__ float t[32][33];
    const int tx = threadIdx.x, ty = threadIdx.y;
    const int n0 = blockIdx.x * 32, k0 = blockIdx.y * 32;
#pragma unroll
    for (int i = 0; i < 4; i++)
        t[ty + 8 * i][tx] = W[(size_t)(k0 + ty + 8 * i) * N + n0 + tx];
    __syncthreads();
#pragma unroll
    for (int i = 0; i < 4; i++) {
        float v = t[tx][ty + 8 * i];
        __nv_bfloat16 h = __float2bfloat16(v);
        size_t idx = (size_t)(n0 + ty + 8 * i) * K + k0 + tx;
        WT_hi[idx] = h;
        WT_lo[idx] = __float2bfloat16(v - __bfloat162float(h));
    }
}

// ============================================================
// impulse response: g_k[c] = C_c . A_c^k . B_c
// ============================================================
__global__ void impulse_kernel(const float* __restrict__ A,
                               const float* __restrict__ Bv,
                               const float* __restrict__ Cv) {
    int c = blockIdx.x * blockDim.x + threadIdx.x;
    if (c >= DINNER) return;
    const float* Ac = A + (size_t)c * DSTATE * DSTATE;
    float h[DSTATE], Cr[DSTATE];
#pragma unroll
    for (int n = 0; n < DSTATE; n++) {
        h[n]  = Bv[c * DSTATE + n];
        Cr[n] = Cv[c * DSTATE + n];
    }
    float y = 0.f;
#pragma unroll
    for (int n = 0; n < DSTATE; n++) y += Cr[n] * h[n];
    g_impT[c] = y;
    for (int k = 1; k < KTAPS; k++) {
        float hn[DSTATE];
#pragma unroll
        for (int n = 0; n < DSTATE; n++) {
            float s = 0.f;
#pragma unroll
            for (int m = 0; m < DSTATE; m++) s += Ac[n * DSTATE + m] * h[m];
            hn[n] = s;
        }
        y = 0.f;
#pragma unroll
        for (int n = 0; n < DSTATE; n++) { h[n] = hn[n]; y += Cr[n] * hn[n]; }
        g_impT[k * DINNER + c] = y;
    }
}

// ============================================================
// bf16x3 GEMM: C[M,N] = (Ah+Al)[M,K] @ (Bh+Bl)[N,K]^T + bias
// 128x128 block, BK=32, 3-stage cp.async pipeline (2 CTAs/SM),
// unpadded 64B rows with XOR-swizzled 16B chunks (conflict-free),
// ldmatrix fragment loads, mma.m16n8k16.bf16 x3 terms.
// ============================================================
template <bool SIG>
__global__ __launch_bounds__(256, 2)
void bf16x3_gemm(const __nv_bfloat16* __restrict__ Ah,
                 const __nv_bfloat16* __restrict__ Al,
                 const __nv_bfloat16* __restrict__ Bh,
                 const __nv_bfloat16* __restrict__ Bl,
                 const float* __restrict__ bias, float* __restrict__ C,
                 int M, int N, int K) {
    extern __shared__ __nv_bfloat16 sm[];
    const uint32_t sm0 = (uint32_t)__cvta_generic_to_shared(sm);

    const int tid = threadIdx.x, warp = tid >> 5, lane = tid & 31;
    const int wm = warp >> 2, wn = warp & 3;
    const int grp = lane >> 2, qid = lane & 3;
    const int m0 = blockIdx.y * 128, n0 = blockIdx.x * 128;

    float acc[4][4][4];
#pragma unroll
    for (int mi = 0; mi < 4; mi++)
#pragma unroll
        for (int ni = 0; ni < 4; ni++)
#pragma unroll
            for (int f = 0; f < 4; f++) acc[mi][ni][f] = 0.f;

    // cp.async mapping: thread -> (row, 32B half = 2 swizzled 16B chunks)
    const int lrow = tid >> 1, lhalf = tid & 1;
    const uint32_t lsw = (lrow >> 1) & 3;
    const __nv_bfloat16* gsrc[4] = {Ah + (size_t)m0 * K, Al + (size_t)m0 * K,
                                    Bh + (size_t)n0 * K, Bl + (size_t)n0 * K};

    // ldmatrix per-lane address components
    const int q = lane >> 3, lr = lane & 7;
    const int a_row = (q & 1) * 8 + lr;  // A: 16-row block, chunk half q>>1
    const int b_row = (q >> 1) * 8 + lr; // B: 16-row block, chunk half q&1

#define TBASE(s, t) (sm0 + (uint32_t)(((s) * 4 + (t)) * TILE_B))
#define LOAD_CHUNK(s, c)                                                       \
    {                                                                          \
        _Pragma("unroll")                                                      \
        for (int t = 0; t < 4; t++) {                                          \
            const __nv_bfloat16* src = gsrc[t] + (size_t)lrow * K + (c) * BK;  \
            const uint32_t dstb = TBASE(s, t) + lrow * 64;                     \
            CP16(dstb + ((((uint32_t)(2 * lhalf + 0)) ^ lsw) << 4),            \
                 src + (2 * lhalf + 0) * 8);                                   \
            CP16(dstb + ((((uint32_t)(2 * lhalf + 1)) ^ lsw) << 4),            \
                 src + (2 * lhalf + 1) * 8);                                   \
        }                                                                      \
        asm volatile("cp.async.commit_group;\n" ::);                           \
    }

    const int KT = K / BK;
    LOAD_CHUNK(0, 0);
    LOAD_CHUNK(1, 1);

    for (int kt = 0; kt < KT; kt++) {
        if (kt + 2 < KT) LOAD_CHUNK((kt + 2) % STAGES, kt + 2);
        const int left = KT - 1 - kt;
        if (left >= 2)      asm volatile("cp.async.wait_group 2;\n" ::);
        else if (left == 1) asm volatile("cp.async.wait_group 1;\n" ::);
        else                asm volatile("cp.async.wait_group 0;\n" ::);
        __syncthreads();

        const int s = kt % STAGES;
#pragma unroll
        for (int kk = 0; kk < 2; kk++) {                 // two k16 steps
            uint32_t ah[4][4], al[4][4], bh[2][4], bl[2][4];
#pragma unroll
            for (int mi = 0; mi < 4; mi++) {
                const uint32_t R = (uint32_t)(wm * 64 + mi * 16 + a_row);
                const uint32_t cl = (uint32_t)(kk * 2 + (q >> 1));
                const uint32_t ro = R * 64 + ((cl ^ ((R >> 1) & 3)) << 4);
                LDM4(ah[mi], TBASE(s, 0) + ro);
                LDM4(al[mi], TBASE(s, 1) + ro);
            }
#pragma unroll
            for (int p = 0; p < 2; p++) {
                const uint32_t R = (uint32_t)(wn * 32 + p * 16 + b_row);
                const uint32_t cl = (uint32_t)(kk * 2 + (q & 1));
                const uint32_t ro = R * 64 + ((cl ^ ((R >> 1) & 3)) << 4);
                LDM4(bh[p], TBASE(s, 2) + ro);
                LDM4(bl[p], TBASE(s, 3) + ro);
            }
#pragma unroll
            for (int mi = 0; mi < 4; mi++)
#pragma unroll
                for (int ni = 0; ni < 4; ni++) {
                    const int p = ni >> 1, o = (ni & 1) * 2;
                    MMA_BF16(acc[mi][ni], ah[mi], bl[p][o], bl[p][o + 1]);
                    MMA_BF16(acc[mi][ni], al[mi], bh[p][o], bh[p][o + 1]);
                    MMA_BF16(acc[mi][ni], ah[mi], bh[p][o], bh[p][o + 1]);
                }
        }
        __syncthreads();
    }

    // epilogue
#pragma unroll
    for (int mi = 0; mi < 4; mi++) {
        const int row = m0 + wm * 64 + mi * 16 + grp;
#pragma unroll
        for (int ni = 0; ni < 4; ni++) {
            const int col = n0 + wn * 32 + ni * 8 + 2 * qid;
            const float b0 = bias[col], b1 = bias[col + 1];
            float v0 = acc[mi][ni][0] + b0;
            float v1 = acc[mi][ni][1] + b1;
            float v2 = acc[mi][ni][2] + b0;
            float v3 = acc[mi][ni][3] + b1;
            if (SIG) {
                v0 = 1.0f / (1.0f + expf(-v0));
                v1 = 1.0f / (1.0f + expf(-v1));
                v2 = 1.0f / (1.0f + expf(-v2));
                v3 = 1.0f / (1.0f + expf(-v3));
            }
            *(float2*)(C + (size_t)row * N + col)       = make_float2(v0, v1);
            *(float2*)(C + (size_t)(row + 8) * N + col) = make_float2(v2, v3);
        }
    }
#undef LOAD_CHUNK
#undef TBASE
}

// ============================================================
// causal 64-tap conv + gate; 32 outputs/thread; writes bf16-split u
// ============================================================
__global__ __launch_bounds__(128)
void conv_gate_kernel() {
    const int tid = threadIdx.x;
    const int c   = blockIdx.y * 128 + tid;
    const int s0  = blockIdx.x * 32;
    const int b   = blockIdx.z;

    float gk[KTAPS];
#pragma unroll
    for (int k = 0; k < KTAPS; k++) gk[k] = g_impT[k * DINNER + c];

    const float* xp = g_xproj + (size_t)b * SEQ * DINNER + c;
    float acc[32];
#pragma unroll
    for (int i = 0; i < 32; i++) acc[i] = 0.f;

    if (s0 >= KTAPS - 1) {
        // steady state: all predicates compile-time
#pragma unroll
        for (int d = -(KTAPS - 1); d <= 31; d++) {
            const float xv = xp[(size_t)(s0 + d) * DINNER];
#pragma unroll
            for (int i = 0; i < 32; i++) {
                const int k = i - d;
                if (k >= 0 && k < KTAPS) acc[i] += gk[k] * xv;
            }
        }
    } else {
        for (int j = 0; j <= s0 + 31; j++) {
            const float xv = xp[(size_t)j * DINNER];
            const int d = j - s0;
#pragma unroll
            for (int i = 0; i < 32; i++) {
                const int k = i - d;
                if (k >= 0 && k < KTAPS) acc[i] += gk[k] * xv;
            }
        }
    }

#pragma unroll
    for (int i = 0; i < 32; i++) {
        const size_t idx = ((size_t)b * SEQ + s0 + i) * DINNER + c;
        const float v = acc[i] * g_gate[idx];
        const __nv_bfloat16 h = __float2bfloat16(v);
        g_uhi[idx] = h;
        g_ulo[idx] = __float2bfloat16(v - __bfloat162float(h));
    }
}

// ============================================================
extern "C" void kernel_launch(void* const* d_in, const int* in_sizes, int n_in,
                              void* d_out, int out_size) {
    const float* x      = (const float*)d_in[0];
    const float* w_in   = (const float*)d_in[1];
    const float* b_in   = (const float*)d_in[2];
    const float* w_gate = (const float*)d_in[3];
    const float* b_gate = (const float*)d_in[4];
    const float* A      = (const float*)d_in[5];
    const float* B_ssm  = (const float*)d_in[6];
    const float* C_ssm  = (const float*)d_in[7];
    const float* w_out  = (const float*)d_in[8];
    const float* b_out  = (const float*)d_in[9];
    float* out = (float*)d_out;

    float *xproj, *gate;
    __nv_bfloat16 *xhi, *xlo, *uhi, *ulo;
    __nv_bfloat16 *wiT_hi, *wiT_lo, *wgT_hi, *wgT_lo, *woT_hi, *woT_lo;
    cudaGetSymbolAddress((void**)&xproj,  g_xproj);
    cudaGetSymbolAddress((void**)&gate,   g_gate);
    cudaGetSymbolAddress((void**)&xhi,    g_xhi);
    cudaGetSymbolAddress((void**)&xlo,    g_xlo);
    cudaGetSymbolAddress((void**)&uhi,    g_uhi);
    cudaGetSymbolAddress((void**)&ulo,    g_ulo);
    cudaGetSymbolAddress((void**)&wiT_hi, g_wiT_hi);
    cudaGetSymbolAddress((void**)&wiT_lo, g_wiT_lo);
    cudaGetSymbolAddress((void**)&wgT_hi, g_wgT_hi);
    cudaGetSymbolAddress((void**)&wgT_lo, g_wgT_lo);
    cudaGetSymbolAddress((void**)&woT_hi, g_woT_hi);
    cudaGetSymbolAddress((void**)&woT_lo, g_woT_lo);

    cudaFuncSetAttribute(bf16x3_gemm<false>,
                         cudaFuncAttributeMaxDynamicSharedMemorySize, SMEM_BYTES);
    cudaFuncSetAttribute(bf16x3_gemm<true>,
                         cudaFuncAttributeMaxDynamicSharedMemorySize, SMEM_BYTES);

    // prep
    const size_t nx = (size_t)MTOT * DMODEL;
    split_kernel<<<(unsigned)((nx / 4 + 255) / 256), 256>>>(x, xhi, xlo, nx);
    wprep_kernel<<<dim3(DINNER / 32, DMODEL / 32), dim3(32, 8)>>>(w_in,   wiT_hi, wiT_lo, DMODEL, DINNER);
    wprep_kernel<<<dim3(DINNER / 32, DMODEL / 32), dim3(32, 8)>>>(w_gate, wgT_hi, wgT_lo, DMODEL, DINNER);
    wprep_kernel<<<dim3(DMODEL / 32, DINNER / 32), dim3(32, 8)>>>(w_out,  woT_hi, woT_lo, DINNER, DMODEL);
    impulse_kernel<<<DINNER / 256, 256>>>(A, B_ssm, C_ssm);

    // GEMM1/2
    dim3 g1(DINNER / 128, MTOT / 128);
    bf16x3_gemm<false><<<g1, 256, SMEM_BYTES>>>(xhi, xlo, wiT_hi, wiT_lo, b_in,
                                                xproj, MTOT, DINNER, DMODEL);
    bf16x3_gemm<true ><<<g1, 256, SMEM_BYTES>>>(xhi, xlo, wgT_hi, wgT_lo, b_gate,
                                                gate, MTOT, DINNER, DMODEL);

    // SSM as 64-tap conv + gating (writes split u)
    conv_gate_kernel<<<dim3(SEQ / 32, DINNER / 128, BATCH), 128>>>();

    // GEMM3
    dim3 g2(DMODEL / 128, MTOT / 128);
    bf16x3_gemm<false><<<g2, 256, SMEM_BYTES>>>(uhi, ulo, woT_hi, woT_lo, b_out,
                                                out, MTOT, DMODEL, DINNER);
}